// round 1
// baseline (speedup 1.0000x reference)
#include <cuda_runtime.h>
#include <math.h>

#define NROWS 4096
#define DDIM  512
#define BM 128
#define BN 128
#define BK 8
#define TM 8
#define TN 8

// Scratch (no cudaMalloc allowed): per-row partial statistics.
__device__ float g_pos_sum[NROWS];
__device__ float g_neg_sum[NROWS];
__device__ float g_pos_cnt[NROWS];
__device__ float g_neg_cnt[NROWS];

__global__ void zero_kernel() {
    int i = blockIdx.x * blockDim.x + threadIdx.x;
    if (i < NROWS) {
        g_pos_sum[i] = 0.f;
        g_neg_sum[i] = 0.f;
        g_pos_cnt[i] = 0.f;
        g_neg_cnt[i] = 0.f;
    }
}

__device__ __forceinline__ float softplus_f(float x) {
    // stable: max(x,0) + log1p(exp(-|x|))
    return fmaxf(x, 0.f) + log1pf(__expf(-fabsf(x)));
}

__global__ void __launch_bounds__(256)
sim_loss_kernel(const float* __restrict__ X, const long long* __restrict__ tgt) {
    __shared__ float As[BK][BM];
    __shared__ float Bs[BK][BN];

    const int I = blockIdx.y * BM;   // row tile
    const int J = blockIdx.x * BN;   // col tile
    const int tid = threadIdx.x;
    const int tx = tid & 15;         // 0..15  -> col group
    const int ty = tid >> 4;         // 0..15  -> row group

    // Global load mapping: 256 threads * 1 float4 = 1024 floats = 128 rows x 8 cols
    const int lrow = tid >> 1;          // 0..127
    const int lcol = (tid & 1) * 4;     // 0 or 4

    float acc[TM][TN];
#pragma unroll
    for (int i = 0; i < TM; i++)
#pragma unroll
        for (int j = 0; j < TN; j++) acc[i][j] = 0.f;

    for (int k0 = 0; k0 < DDIM; k0 += BK) {
        float4 av = *(const float4*)&X[(size_t)(I + lrow) * DDIM + k0 + lcol];
        float4 bv = *(const float4*)&X[(size_t)(J + lrow) * DDIM + k0 + lcol];
        __syncthreads();   // previous tile fully consumed
        As[lcol + 0][lrow] = av.x;
        As[lcol + 1][lrow] = av.y;
        As[lcol + 2][lrow] = av.z;
        As[lcol + 3][lrow] = av.w;
        Bs[lcol + 0][lrow] = bv.x;
        Bs[lcol + 1][lrow] = bv.y;
        Bs[lcol + 2][lrow] = bv.z;
        Bs[lcol + 3][lrow] = bv.w;
        __syncthreads();

#pragma unroll
        for (int kk = 0; kk < BK; kk++) {
            float a[TM], b[TN];
#pragma unroll
            for (int i = 0; i < TM; i += 4) {
                float4 v = *(const float4*)&As[kk][ty * TM + i];
                a[i] = v.x; a[i + 1] = v.y; a[i + 2] = v.z; a[i + 3] = v.w;
            }
#pragma unroll
            for (int j = 0; j < TN; j += 4) {
                float4 v = *(const float4*)&Bs[kk][tx * TN + j];
                b[j] = v.x; b[j + 1] = v.y; b[j + 2] = v.z; b[j + 3] = v.w;
            }
#pragma unroll
            for (int i = 0; i < TM; i++)
#pragma unroll
                for (int j = 0; j < TN; j++)
                    acc[i][j] = fmaf(a[i], b[j], acc[i][j]);
        }
    }

    // ---- fused epilogue: per-row masked statistics ----
    const int r_base = I + ty * TM;
    const int c_base = J + tx * TN;
    int trow[TM], tcol[TN];
#pragma unroll
    for (int i = 0; i < TM; i++) trow[i] = (int)tgt[r_base + i];
#pragma unroll
    for (int j = 0; j < TN; j++) tcol[j] = (int)tgt[c_base + j];

#pragma unroll
    for (int i = 0; i < TM; i++) {
        float ps = 0.f, ns = 0.f, pc = 0.f, nc = 0.f;
#pragma unroll
        for (int j = 0; j < TN; j++) {
            float s = acc[i][j];
            if (trow[i] == tcol[j]) {
                if (s < 1.0f) {
                    pc += 1.f;
                    ps += softplus_f(-2.0f * (s - 0.5f));
                }
            } else {
                nc += 1.f;
                ns += softplus_f(25.0f * (s - 0.5f));
            }
        }
        // reduce across the 16 tx threads (they sit in one half-warp: lane = (ty&1)*16 + tx)
#pragma unroll
        for (int off = 8; off > 0; off >>= 1) {
            ps += __shfl_down_sync(0xffffffffu, ps, off, 16);
            ns += __shfl_down_sync(0xffffffffu, ns, off, 16);
            pc += __shfl_down_sync(0xffffffffu, pc, off, 16);
            nc += __shfl_down_sync(0xffffffffu, nc, off, 16);
        }
        if (tx == 0) {
            int r = r_base + i;
            atomicAdd(&g_pos_sum[r], ps);
            atomicAdd(&g_neg_sum[r], ns);
            atomicAdd(&g_pos_cnt[r], pc);
            atomicAdd(&g_neg_cnt[r], nc);
        }
    }
}

__global__ void __launch_bounds__(256) finalize_kernel(float* out) {
    __shared__ float red[256];
    float local = 0.f;
    for (int r = threadIdx.x; r < NROWS; r += 256) {
        float pc = g_pos_cnt[r], nc = g_neg_cnt[r];
        float pm = (pc > 0.f) ? g_pos_sum[r] / fmaxf(pc, 1.f) : 0.f;
        float nm = (nc > 0.f) ? g_neg_sum[r] / fmaxf(nc, 1.f) : 0.f;
        local += pm + nm;
    }
    red[threadIdx.x] = local;
    __syncthreads();
    for (int off = 128; off > 0; off >>= 1) {
        if (threadIdx.x < off) red[threadIdx.x] += red[threadIdx.x + off];
        __syncthreads();
    }
    if (threadIdx.x == 0) out[0] = red[0] / (float)NROWS;
}

extern "C" void kernel_launch(void* const* d_in, const int* in_sizes, int n_in,
                              void* d_out, int out_size) {
    const float* X = (const float*)d_in[0];
    const long long* tgt = (const long long*)d_in[1];
    float* out = (float*)d_out;

    zero_kernel<<<(NROWS + 255) / 256, 256>>>();
    dim3 grid(NROWS / BN, NROWS / BM);
    sim_loss_kernel<<<grid, 256>>>(X, tgt);
    finalize_kernel<<<1, 256>>>(out);
}

// round 2
// speedup vs baseline: 1.7257x; 1.7257x over previous
#include <cuda_runtime.h>
#include <math.h>

#define NROWS 4096
#define DDIM  512
#define BM 128
#define BN 128
#define BK 8
#define TM 8
#define TN 8

// Scratch (no cudaMalloc allowed): per-row partial statistics.
__device__ float g_pos_sum[NROWS];
__device__ float g_neg_sum[NROWS];
__device__ float g_pos_cnt[NROWS];
__device__ float g_neg_cnt[NROWS];

__global__ void zero_kernel() {
    int i = blockIdx.x * blockDim.x + threadIdx.x;
    if (i < NROWS) {
        g_pos_sum[i] = 0.f;
        g_neg_sum[i] = 0.f;
        g_pos_cnt[i] = 0.f;
        g_neg_cnt[i] = 0.f;
    }
}

__device__ __forceinline__ float softplus_f(float x) {
    // stable: max(x,0) + log1p(exp(-|x|))
    return fmaxf(x, 0.f) + log1pf(__expf(-fabsf(x)));
}

__global__ void __launch_bounds__(256)
sim_loss_kernel(const float* __restrict__ X, const long long* __restrict__ tgt) {
    const int bi = blockIdx.y;   // row tile index
    const int bj = blockIdx.x;   // col tile index
    if (bj < bi) return;         // only upper triangle (incl. diagonal)

    __shared__ float As[BK][BM];
    __shared__ float Bs[BK][BN];
    __shared__ float colred[8][4][128];   // [warp][stat][col]

    const int I = bi * BM;
    const int J = bj * BN;
    const int tid = threadIdx.x;
    const int tx = tid & 15;         // 0..15  -> col group
    const int ty = tid >> 4;         // 0..15  -> row group

    // Global load mapping: 256 threads * 1 float4 = 1024 floats = 128 rows x 8 cols
    const int lrow = tid >> 1;          // 0..127
    const int lcol = (tid & 1) * 4;     // 0 or 4

    float acc[TM][TN];
#pragma unroll
    for (int i = 0; i < TM; i++)
#pragma unroll
        for (int j = 0; j < TN; j++) acc[i][j] = 0.f;

    for (int k0 = 0; k0 < DDIM; k0 += BK) {
        float4 av = *(const float4*)&X[(size_t)(I + lrow) * DDIM + k0 + lcol];
        float4 bv = *(const float4*)&X[(size_t)(J + lrow) * DDIM + k0 + lcol];
        __syncthreads();   // previous tile fully consumed
        As[lcol + 0][lrow] = av.x;
        As[lcol + 1][lrow] = av.y;
        As[lcol + 2][lrow] = av.z;
        As[lcol + 3][lrow] = av.w;
        Bs[lcol + 0][lrow] = bv.x;
        Bs[lcol + 1][lrow] = bv.y;
        Bs[lcol + 2][lrow] = bv.z;
        Bs[lcol + 3][lrow] = bv.w;
        __syncthreads();

#pragma unroll
        for (int kk = 0; kk < BK; kk++) {
            float a[TM], b[TN];
#pragma unroll
            for (int i = 0; i < TM; i += 4) {
                float4 v = *(const float4*)&As[kk][ty * TM + i];
                a[i] = v.x; a[i + 1] = v.y; a[i + 2] = v.z; a[i + 3] = v.w;
            }
#pragma unroll
            for (int j = 0; j < TN; j += 4) {
                float4 v = *(const float4*)&Bs[kk][tx * TN + j];
                b[j] = v.x; b[j + 1] = v.y; b[j + 2] = v.z; b[j + 3] = v.w;
            }
#pragma unroll
            for (int i = 0; i < TM; i++)
#pragma unroll
                for (int j = 0; j < TN; j++)
                    acc[i][j] = fmaf(a[i], b[j], acc[i][j]);
        }
    }

    // ---- fused epilogue ----
    const int r_base = I + ty * TM;
    const int c_base = J + tx * TN;
    int trow[TM], tcol[TN];
#pragma unroll
    for (int i = 0; i < TM; i++) trow[i] = (int)tgt[r_base + i];
#pragma unroll
    for (int j = 0; j < TN; j++) tcol[j] = (int)tgt[c_base + j];

    // Pass A: row statistics (rows r_base..r_base+7, columns of this tile)
#pragma unroll
    for (int i = 0; i < TM; i++) {
        float ps = 0.f, ns = 0.f, pc = 0.f, nc = 0.f;
#pragma unroll
        for (int j = 0; j < TN; j++) {
            float s = acc[i][j];
            if (trow[i] == tcol[j]) {
                if (s < 1.0f) {
                    pc += 1.f;
                    ps += softplus_f(-2.0f * (s - 0.5f));
                }
            } else {
                nc += 1.f;
                ns += softplus_f(25.0f * (s - 0.5f));
            }
        }
        // reduce across the 16 tx threads (contiguous lanes within a half-warp)
#pragma unroll
        for (int off = 8; off > 0; off >>= 1) {
            ps += __shfl_down_sync(0xffffffffu, ps, off, 16);
            ns += __shfl_down_sync(0xffffffffu, ns, off, 16);
            pc += __shfl_down_sync(0xffffffffu, pc, off, 16);
            nc += __shfl_down_sync(0xffffffffu, nc, off, 16);
        }
        if (tx == 0) {
            int r = r_base + i;
            atomicAdd(&g_pos_sum[r], ps);
            atomicAdd(&g_neg_sum[r], ns);
            atomicAdd(&g_pos_cnt[r], pc);
            atomicAdd(&g_neg_cnt[r], nc);
        }
    }

    // Pass B: column statistics -> contributions to rows J..J+127 (transpose side).
    // Only for strictly off-diagonal tiles; the mirror tile (bj,bi) is never launched.
    if (bi != bj) {
        const int w = tid >> 5;   // warp id 0..7
#pragma unroll
        for (int j = 0; j < TN; j++) {
            float ps = 0.f, ns = 0.f, pc = 0.f, nc = 0.f;
#pragma unroll
            for (int i = 0; i < TM; i++) {
                float s = acc[i][j];
                if (trow[i] == tcol[j]) {
                    if (s < 1.0f) {
                        pc += 1.f;
                        ps += softplus_f(-2.0f * (s - 0.5f));
                    }
                } else {
                    nc += 1.f;
                    ns += softplus_f(25.0f * (s - 0.5f));
                }
            }
            // combine the two ty values in this warp: lanes l and l+16 share tx
            ps += __shfl_down_sync(0xffffffffu, ps, 16);
            ns += __shfl_down_sync(0xffffffffu, ns, 16);
            pc += __shfl_down_sync(0xffffffffu, pc, 16);
            nc += __shfl_down_sync(0xffffffffu, nc, 16);
            if ((tid & 16) == 0) {        // lower half of the warp holds the pair sum
                int col = tx * TN + j;    // 0..127 (distinct per lane, per j)
                colred[w][0][col] = ps;
                colred[w][1][col] = ns;
                colred[w][2][col] = pc;
                colred[w][3][col] = nc;
            }
        }
        __syncthreads();
        // Reduce the 8 per-warp partials; 512 (stat,col) cells over 256 threads.
#pragma unroll
        for (int v = tid; v < 4 * 128; v += 256) {
            int stat = v >> 7;
            int col = v & 127;
            float sum = 0.f;
#pragma unroll
            for (int ww = 0; ww < 8; ww++) sum += colred[ww][stat][col];
            int r = J + col;
            if (stat == 0)      atomicAdd(&g_pos_sum[r], sum);
            else if (stat == 1) atomicAdd(&g_neg_sum[r], sum);
            else if (stat == 2) atomicAdd(&g_pos_cnt[r], sum);
            else                atomicAdd(&g_neg_cnt[r], sum);
        }
    }
}

__global__ void __launch_bounds__(256) finalize_kernel(float* out) {
    __shared__ float red[256];
    float local = 0.f;
    for (int r = threadIdx.x; r < NROWS; r += 256) {
        float pc = g_pos_cnt[r], nc = g_neg_cnt[r];
        float pm = (pc > 0.f) ? g_pos_sum[r] / fmaxf(pc, 1.f) : 0.f;
        float nm = (nc > 0.f) ? g_neg_sum[r] / fmaxf(nc, 1.f) : 0.f;
        local += pm + nm;
    }
    red[threadIdx.x] = local;
    __syncthreads();
    for (int off = 128; off > 0; off >>= 1) {
        if (threadIdx.x < off) red[threadIdx.x] += red[threadIdx.x + off];
        __syncthreads();
    }
    if (threadIdx.x == 0) out[0] = red[0] / (float)NROWS;
}

extern "C" void kernel_launch(void* const* d_in, const int* in_sizes, int n_in,
                              void* d_out, int out_size) {
    const float* X = (const float*)d_in[0];
    const long long* tgt = (const long long*)d_in[1];
    float* out = (float*)d_out;

    zero_kernel<<<(NROWS + 255) / 256, 256>>>();
    dim3 grid(NROWS / BN, NROWS / BM);
    sim_loss_kernel<<<grid, 256>>>(X, tgt);
    finalize_kernel<<<1, 256>>>(out);
}

// round 7
// speedup vs baseline: 3.6751x; 2.1296x over previous
#include <cuda_runtime.h>
#include <cuda_bf16.h>
#include <math.h>
#include <stdint.h>

#define NROWS 4096
#define DDIM  512
#define BM 128
#define BN 128
#define NCH  16                 // 16 k-chunks of 32 elements (64 bytes)
#define ROWB 80                 // smem row stride: 64B data + 16B pad (LDSM conflict-free)
#define TILEB (128 * ROWB)      // 10240 B per operand tile

// ---- scratch (no cudaMalloc allowed) ----
__device__ __align__(16) __nv_bfloat16 g_hi[NROWS * DDIM];
__device__ __align__(16) __nv_bfloat16 g_lo[NROWS * DDIM];
__device__ float g_ps[NROWS];
__device__ float g_ns[NROWS];
__device__ float g_pc[NROWS];
__device__ float g_nc[NROWS];

__device__ __forceinline__ uint32_t smem_u32(const void* p) {
    return (uint32_t)__cvta_generic_to_shared(p);
}

__device__ __forceinline__ float softplus_f(float x) {
    return fmaxf(x, 0.f) + __logf(1.f + __expf(-fabsf(x)));
}

#define LDSM4(R, ADDR)                                                         \
    asm volatile("ldmatrix.sync.aligned.m8n8.x4.shared.b16 {%0,%1,%2,%3}, [%4];" \
                 : "=r"((R)[0]), "=r"((R)[1]), "=r"((R)[2]), "=r"((R)[3])      \
                 : "r"(ADDR))

#define MMA16816(C, A0, A1, A2, A3, B0, B1)                                    \
    asm volatile("mma.sync.aligned.m16n8k16.row.col.f32.bf16.bf16.f32 "        \
                 "{%0,%1,%2,%3}, {%4,%5,%6,%7}, {%8,%9}, {%0,%1,%2,%3};"       \
                 : "+f"((C)[0]), "+f"((C)[1]), "+f"((C)[2]), "+f"((C)[3])      \
                 : "r"(A0), "r"(A1), "r"(A2), "r"(A3), "r"(B0), "r"(B1))

// ============================================================================
// prep: fp32 -> bf16 hi/lo split; zeros per-row stat arrays
// ============================================================================
__global__ void __launch_bounds__(256) prep_kernel(const float* __restrict__ X) {
    int i = blockIdx.x * blockDim.x + threadIdx.x;
    int base = i * 4;
    if (base < NROWS * DDIM) {
        float4 v = *(const float4*)&X[base];
        float f[4] = {v.x, v.y, v.z, v.w};
#pragma unroll
        for (int k = 0; k < 4; k++) {
            __nv_bfloat16 h = __float2bfloat16(f[k]);
            g_hi[base + k] = h;
            g_lo[base + k] = __float2bfloat16(f[k] - __bfloat162float(h));
        }
    }
    if (i < NROWS) { g_ps[i] = 0.f; g_ns[i] = 0.f; g_pc[i] = 0.f; g_nc[i] = 0.f; }
}

// ============================================================================
// main: bf16 hi/lo-split mma.sync GEMM + fused softplus stats, upper triangle
// Static smem only (45 KB), synchronous tile fill, no cp.async.
// ============================================================================
__global__ void __launch_bounds__(256, 2)
sim_loss_mma(const long long* __restrict__ tgt) {
    const int bi = blockIdx.y, bj = blockIdx.x;
    if (bj < bi) return;   // upper triangle incl. diagonal
    const bool offdiag = (bi != bj);

    __shared__ __align__(16) char s_tiles[4 * TILEB];      // Ahi, Alo, Bhi, Blo
    __shared__ int   s_ti[128], s_tj[128];
    __shared__ float s_rps[128], s_rns[128], s_rpc[128], s_rnc[128];
    __shared__ float s_cps[128], s_cns[128], s_cpc[128], s_cnc[128];

    const int tid  = threadIdx.x;
    const int wid  = tid >> 5;
    const int lane = tid & 31;
    const int warp_m = wid & 3;    // 4 warps along M (32 rows each)
    const int warp_n = wid >> 2;   // 2 warps along N (64 cols each)

    if (tid < 128) {
        s_ti[tid] = (int)tgt[bi * BM + tid];
        s_rps[tid] = 0.f; s_rns[tid] = 0.f; s_rpc[tid] = 0.f; s_rnc[tid] = 0.f;
    } else {
        s_tj[tid - 128] = (int)tgt[bj * BN + tid - 128];
        s_cps[tid - 128] = 0.f; s_cns[tid - 128] = 0.f;
        s_cpc[tid - 128] = 0.f; s_cnc[tid - 128] = 0.f;
    }

    const char* src[4];
    src[0] = (const char*)(g_hi + (size_t)bi * BM * DDIM);   // Ahi
    src[1] = (const char*)(g_lo + (size_t)bi * BM * DDIM);   // Alo
    src[2] = (const char*)(g_hi + (size_t)bj * BN * DDIM);   // Bhi
    src[3] = (const char*)(g_lo + (size_t)bj * BN * DDIM);   // Blo

    const uint32_t stile = smem_u32(s_tiles);
    const uint32_t a_off0 = (uint32_t)((warp_m * 32 + (lane & 15)) * ROWB + (lane >> 4) * 16);
    const uint32_t b_off0 = (uint32_t)(
        (warp_n * 64 + ((lane >> 4) << 3) + (lane & 7)) * ROWB + ((lane >> 3) & 1) * 16);

    float acc[2][8][4];
#pragma unroll
    for (int mi = 0; mi < 2; mi++)
#pragma unroll
        for (int ni = 0; ni < 8; ni++)
#pragma unroll
            for (int x = 0; x < 4; x++) acc[mi][ni][x] = 0.f;

    const int frow = tid >> 1;                // 0..127: fill row
    const int fq   = (tid & 1) * 2;           // 16B-quad pair base {0, 2}

    for (int c = 0; c < NCH; c++) {
        // ---- fill: 4 tiles x 128 rows x 64B; each thread 8 x 16B ----
#pragma unroll
        for (int t = 0; t < 4; t++) {
            const char* gsrc = src[t] + frow * 1024 + c * 64 + fq * 16;
            float4 v0 = *(const float4*)(gsrc);
            float4 v1 = *(const float4*)(gsrc + 16);
            char* dst = s_tiles + t * TILEB + frow * ROWB + fq * 16;
            *(float4*)(dst)      = v0;
            *(float4*)(dst + 16) = v1;
        }
        __syncthreads();

        // ---- compute: two k16 steps over this 64B chunk ----
#pragma unroll
        for (int ks = 0; ks < 2; ks++) {
            uint32_t ah[2][4], al[2][4];
#pragma unroll
            for (int mi = 0; mi < 2; mi++) {
                const uint32_t ao = a_off0 + (uint32_t)(mi * 16 * ROWB + ks * 32);
                LDSM4(ah[mi], stile + 0 * TILEB + ao);
                LDSM4(al[mi], stile + 1 * TILEB + ao);
            }
#pragma unroll
            for (int ng = 0; ng < 4; ng++) {
                uint32_t bh[4], bl[4];
                const uint32_t bo = b_off0 + (uint32_t)(ng * 16 * ROWB + ks * 32);
                LDSM4(bh, stile + 2 * TILEB + bo);
                LDSM4(bl, stile + 3 * TILEB + bo);
#pragma unroll
                for (int mi = 0; mi < 2; mi++) {
                    float* c0 = acc[mi][ng * 2 + 0];
                    float* c1 = acc[mi][ng * 2 + 1];
                    MMA16816(c0, ah[mi][0], ah[mi][1], ah[mi][2], ah[mi][3], bh[0], bh[1]);
                    MMA16816(c1, ah[mi][0], ah[mi][1], ah[mi][2], ah[mi][3], bh[2], bh[3]);
                    MMA16816(c0, ah[mi][0], ah[mi][1], ah[mi][2], ah[mi][3], bl[0], bl[1]);
                    MMA16816(c1, ah[mi][0], ah[mi][1], ah[mi][2], ah[mi][3], bl[2], bl[3]);
                    MMA16816(c0, al[mi][0], al[mi][1], al[mi][2], al[mi][3], bh[0], bh[1]);
                    MMA16816(c1, al[mi][0], al[mi][1], al[mi][2], al[mi][3], bh[2], bh[3]);
                }
            }
        }
        __syncthreads();   // all reads done before next fill overwrites
    }

    // ================= fused epilogue (R2-proven 4-stat scheme) =================
    const int laneq = lane >> 2, lane4 = lane & 3;
    int tr[4];
#pragma unroll
    for (int ri = 0; ri < 4; ri++)
        tr[ri] = s_ti[warp_m * 32 + (ri >> 1) * 16 + laneq + (ri & 1) * 8];

    float rps[4] = {0,0,0,0}, rns[4] = {0,0,0,0}, rpc[4] = {0,0,0,0}, rnc[4] = {0,0,0,0};

#pragma unroll
    for (int ni = 0; ni < 8; ni++) {
#pragma unroll
        for (int cb = 0; cb < 2; cb++) {
            const int col = warp_n * 64 + ni * 8 + lane4 * 2 + cb;
            const int tc = s_tj[col];
            float cps = 0.f, cns = 0.f, cpc = 0.f, cnc = 0.f;
#pragma unroll
            for (int mi = 0; mi < 2; mi++)
#pragma unroll
                for (int half = 0; half < 2; half++) {
                    const float sv = acc[mi][ni][half * 2 + cb];
                    const int ri = mi * 2 + half;
                    if (tr[ri] == tc) {
                        if (sv < 1.f) {
                            float p = softplus_f(-2.f * (sv - 0.5f));
                            rps[ri] += p; cps += p;
                            rpc[ri] += 1.f; cpc += 1.f;
                        }
                    } else {
                        float nterm = softplus_f(25.f * (sv - 0.5f));
                        rns[ri] += nterm; cns += nterm;
                        rnc[ri] += 1.f; cnc += 1.f;
                    }
                }
            if (offdiag) {
#pragma unroll
                for (int o = 4; o < 32; o <<= 1) {
                    cps += __shfl_xor_sync(0xffffffffu, cps, o);
                    cns += __shfl_xor_sync(0xffffffffu, cns, o);
                    cpc += __shfl_xor_sync(0xffffffffu, cpc, o);
                    cnc += __shfl_xor_sync(0xffffffffu, cnc, o);
                }
                if (laneq == 0) {
                    atomicAdd(&s_cns[col], cns);
                    atomicAdd(&s_cnc[col], cnc);
                    if (cpc != 0.f) {
                        atomicAdd(&s_cps[col], cps);
                        atomicAdd(&s_cpc[col], cpc);
                    }
                }
            }
        }
    }
#pragma unroll
    for (int ri = 0; ri < 4; ri++) {
        float p = rps[ri], a = rns[ri], q = rpc[ri], b = rnc[ri];
        p += __shfl_xor_sync(0xffffffffu, p, 1); p += __shfl_xor_sync(0xffffffffu, p, 2);
        a += __shfl_xor_sync(0xffffffffu, a, 1); a += __shfl_xor_sync(0xffffffffu, a, 2);
        q += __shfl_xor_sync(0xffffffffu, q, 1); q += __shfl_xor_sync(0xffffffffu, q, 2);
        b += __shfl_xor_sync(0xffffffffu, b, 1); b += __shfl_xor_sync(0xffffffffu, b, 2);
        if (lane4 == 0) {
            const int r = warp_m * 32 + (ri >> 1) * 16 + laneq + (ri & 1) * 8;
            atomicAdd(&s_rns[r], a);
            atomicAdd(&s_rnc[r], b);
            if (q != 0.f) {
                atomicAdd(&s_rps[r], p);
                atomicAdd(&s_rpc[r], q);
            }
        }
    }
    __syncthreads();

    if (tid < 128) {
        const int r = bi * BM + tid;
        atomicAdd(&g_ns[r], s_rns[tid]);
        atomicAdd(&g_nc[r], s_rnc[tid]);
        if (s_rpc[tid] != 0.f) {
            atomicAdd(&g_ps[r], s_rps[tid]);
            atomicAdd(&g_pc[r], s_rpc[tid]);
        }
    } else if (offdiag) {
        const int t2 = tid - 128;
        const int cidx = bj * BN + t2;
        atomicAdd(&g_ns[cidx], s_cns[t2]);
        atomicAdd(&g_nc[cidx], s_cnc[t2]);
        if (s_cpc[t2] != 0.f) {
            atomicAdd(&g_ps[cidx], s_cps[t2]);
            atomicAdd(&g_pc[cidx], s_cpc[t2]);
        }
    }
}

// ============================================================================
// finalize: per-row means; global mean (R2-proven)
// ============================================================================
__global__ void __launch_bounds__(256) finalize_kernel(float* out) {
    __shared__ float red[256];
    float local = 0.f;
    for (int r = threadIdx.x; r < NROWS; r += 256) {
        float pc = g_pc[r], nc = g_nc[r];
        float pm = (pc > 0.f) ? g_ps[r] / fmaxf(pc, 1.f) : 0.f;
        float nm = (nc > 0.f) ? g_ns[r] / fmaxf(nc, 1.f) : 0.f;
        local += pm + nm;
    }
    red[threadIdx.x] = local;
    __syncthreads();
    for (int off = 128; off > 0; off >>= 1) {
        if (threadIdx.x < off) red[threadIdx.x] += red[threadIdx.x + off];
        __syncthreads();
    }
    if (threadIdx.x == 0) out[0] = red[0] / (float)NROWS;
}

extern "C" void kernel_launch(void* const* d_in, const int* in_sizes, int n_in,
                              void* d_out, int out_size) {
    const float* X = (const float*)d_in[0];
    const long long* tgt = (const long long*)d_in[1];
    float* out = (float*)d_out;

    prep_kernel<<<(NROWS * DDIM / 4 + 255) / 256, 256>>>(X);
    dim3 grid(NROWS / BN, NROWS / BM);
    sim_loss_mma<<<grid, 256>>>(tgt);
    finalize_kernel<<<1, 256>>>(out);
}

// round 9
// speedup vs baseline: 3.9688x; 1.0799x over previous
#include <cuda_runtime.h>
#include <cuda_bf16.h>
#include <math.h>
#include <stdint.h>

#define NROWS 4096
#define DDIM  512
#define BM 128
#define BN 128
#define NSUB 32                 // 32 k16 sub-chunks (32 B per row each)
#define ROWB 32                 // smem row stride (XOR swizzle, no pad)
#define TILEB (128 * ROWB)      // 4096 B per operand tile
#define STAGEB (4 * TILEB)      // Ahi, Alo, Bhi, Blo = 16384 B

// ---- scratch (no cudaMalloc allowed) ----
__device__ __align__(16) __nv_bfloat16 g_hi[NROWS * DDIM];
__device__ __align__(16) __nv_bfloat16 g_lo[NROWS * DDIM];
__device__ float g_ps[NROWS];
__device__ float g_ns[NROWS];
__device__ float g_pc[NROWS];
__device__ float g_nc[NROWS];

__device__ __forceinline__ uint32_t smem_u32(const void* p) {
    return (uint32_t)__cvta_generic_to_shared(p);
}

__device__ __forceinline__ float softplus_f(float x) {
    return fmaxf(x, 0.f) + __logf(1.f + __expf(-fabsf(x)));
}

#define LDSM4(R, ADDR)                                                         \
    asm volatile("ldmatrix.sync.aligned.m8n8.x4.shared.b16 {%0,%1,%2,%3}, [%4];" \
                 : "=r"((R)[0]), "=r"((R)[1]), "=r"((R)[2]), "=r"((R)[3])      \
                 : "r"(ADDR))

#define MMA16816(C, A0, A1, A2, A3, B0, B1)                                    \
    asm volatile("mma.sync.aligned.m16n8k16.row.col.f32.bf16.bf16.f32 "        \
                 "{%0,%1,%2,%3}, {%4,%5,%6,%7}, {%8,%9}, {%0,%1,%2,%3};"       \
                 : "+f"((C)[0]), "+f"((C)[1]), "+f"((C)[2]), "+f"((C)[3])      \
                 : "r"(A0), "r"(A1), "r"(A2), "r"(A3), "r"(B0), "r"(B1))

// ============================================================================
// prep: fp32 -> bf16 hi/lo split; zeros per-row stat arrays
// ============================================================================
__global__ void __launch_bounds__(256) prep_kernel(const float* __restrict__ X) {
    int i = blockIdx.x * blockDim.x + threadIdx.x;
    int base = i * 4;
    if (base < NROWS * DDIM) {
        float4 v = *(const float4*)&X[base];
        float f[4] = {v.x, v.y, v.z, v.w};
#pragma unroll
        for (int k = 0; k < 4; k++) {
            __nv_bfloat16 h = __float2bfloat16(f[k]);
            g_hi[base + k] = h;
            g_lo[base + k] = __float2bfloat16(f[k] - __bfloat162float(h));
        }
    }
    if (i < NROWS) { g_ps[i] = 0.f; g_ns[i] = 0.f; g_pc[i] = 0.f; g_nc[i] = 0.f; }
}

// ============================================================================
// main: bf16 hi/lo-split mma.sync GEMM + fused softplus stats, upper triangle.
// Static smem, double-buffered via register prefetch (LDG->reg->STS), no cp.async.
// ============================================================================
__global__ void __launch_bounds__(256, 2)
sim_loss_mma(const long long* __restrict__ tgt) {
    const int bi = blockIdx.y, bj = blockIdx.x;
    if (bj < bi) return;   // upper triangle incl. diagonal
    const bool offdiag = (bi != bj);

    __shared__ __align__(16) char s_tiles[2 * STAGEB];   // 32 KB, 2 stages
    __shared__ int   s_ti[128], s_tj[128];
    __shared__ float s_rps[128], s_rns[128], s_rpc[128], s_rnc[128];
    __shared__ float s_cps[128], s_cns[128], s_cpc[128], s_cnc[128];

    const int tid  = threadIdx.x;
    const int wid  = tid >> 5;
    const int lane = tid & 31;
    const int warp_m = wid & 3;    // 4 warps along M (32 rows each)
    const int warp_n = wid >> 2;   // 2 warps along N (64 cols each)

    if (tid < 128) {
        s_ti[tid] = (int)tgt[bi * BM + tid];
        s_rps[tid] = 0.f; s_rns[tid] = 0.f; s_rpc[tid] = 0.f; s_rnc[tid] = 0.f;
    } else {
        s_tj[tid - 128] = (int)tgt[bj * BN + tid - 128];
        s_cps[tid - 128] = 0.f; s_cns[tid - 128] = 0.f;
        s_cpc[tid - 128] = 0.f; s_cnc[tid - 128] = 0.f;
    }

    const char* src0 = (const char*)(g_hi + (size_t)bi * BM * DDIM);   // Ahi
    const char* src1 = (const char*)(g_lo + (size_t)bi * BM * DDIM);   // Alo
    const char* src2 = (const char*)(g_hi + (size_t)bj * BN * DDIM);   // Bhi
    const char* src3 = (const char*)(g_lo + (size_t)bj * BN * DDIM);   // Blo

    // per-thread fill coords: 128 rows x 2 sixteen-byte quads per tile
    const int frow = tid >> 1;
    const int fqb  = (tid & 1) * 16;
    const uint32_t fso = ((uint32_t)(frow * ROWB + fqb)) ^ (((uint32_t)frow & 4u) << 2);
    char* fdst = s_tiles + fso;
    const char* fsrc_base0 = src0 + frow * 1024 + fqb;
    const char* fsrc_base1 = src1 + frow * 1024 + fqb;
    const char* fsrc_base2 = src2 + frow * 1024 + fqb;
    const char* fsrc_base3 = src3 + frow * 1024 + fqb;

    const uint32_t stile = smem_u32(s_tiles);
    // ldmatrix lane offsets (XOR swizzle folded; +mi/+ng row steps preserve bit)
    const uint32_t a_off0 = (((uint32_t)((warp_m * 32 + (lane & 15)) * ROWB + (lane >> 4) * 16))
                             ^ (((uint32_t)lane & 4u) << 2));
    const int browb = warp_n * 64 + ((lane >> 4) << 3) + (lane & 7);
    const uint32_t b_off0 = (((uint32_t)(browb * ROWB + ((lane >> 3) & 1) * 16))
                             ^ (((uint32_t)lane & 4u) << 2));

    float acc[2][8][4];
#pragma unroll
    for (int mi = 0; mi < 2; mi++)
#pragma unroll
        for (int ni = 0; ni < 8; ni++)
#pragma unroll
            for (int x = 0; x < 4; x++) acc[mi][ni][x] = 0.f;

    // ---- prologue: fetch sub 0 and store into stage 0 ----
    float4 pf0 = *(const float4*)(fsrc_base0);
    float4 pf1 = *(const float4*)(fsrc_base1);
    float4 pf2 = *(const float4*)(fsrc_base2);
    float4 pf3 = *(const float4*)(fsrc_base3);
    *(float4*)(fdst + 0 * TILEB) = pf0;
    *(float4*)(fdst + 1 * TILEB) = pf1;
    *(float4*)(fdst + 2 * TILEB) = pf2;
    *(float4*)(fdst + 3 * TILEB) = pf3;

    for (int sub = 0; sub < NSUB; sub++) {
        __syncthreads();   // stage sub&1 fully written; stage^1 reads (iter sub-1) done

        const bool more = (sub + 1 < NSUB);
        if (more) {        // issue global loads early; consumed at bottom of loop
            const int go = (sub + 1) * 32;
            pf0 = *(const float4*)(fsrc_base0 + go);
            pf1 = *(const float4*)(fsrc_base1 + go);
            pf2 = *(const float4*)(fsrc_base2 + go);
            pf3 = *(const float4*)(fsrc_base3 + go);
        }

        const uint32_t st = stile + (uint32_t)(sub & 1) * STAGEB;
        uint32_t ah[2][4], al[2][4];
#pragma unroll
        for (int mi = 0; mi < 2; mi++) {
            const uint32_t ao = a_off0 + (uint32_t)(mi * 16 * ROWB);
            LDSM4(ah[mi], st + 0 * TILEB + ao);
            LDSM4(al[mi], st + 1 * TILEB + ao);
        }
#pragma unroll
        for (int ng = 0; ng < 4; ng++) {
            uint32_t bh[4], bl[4];
            const uint32_t bo = b_off0 + (uint32_t)(ng * 16 * ROWB);
            LDSM4(bh, st + 2 * TILEB + bo);
            LDSM4(bl, st + 3 * TILEB + bo);
#pragma unroll
            for (int mi = 0; mi < 2; mi++) {
                float* c0 = acc[mi][ng * 2 + 0];
                float* c1 = acc[mi][ng * 2 + 1];
                MMA16816(c0, ah[mi][0], ah[mi][1], ah[mi][2], ah[mi][3], bh[0], bh[1]);
                MMA16816(c1, ah[mi][0], ah[mi][1], ah[mi][2], ah[mi][3], bh[2], bh[3]);
                MMA16816(c0, ah[mi][0], ah[mi][1], ah[mi][2], ah[mi][3], bl[0], bl[1]);
                MMA16816(c1, ah[mi][0], ah[mi][1], ah[mi][2], ah[mi][3], bl[2], bl[3]);
                MMA16816(c0, al[mi][0], al[mi][1], al[mi][2], al[mi][3], bh[0], bh[1]);
                MMA16816(c1, al[mi][0], al[mi][1], al[mi][2], al[mi][3], bh[2], bh[3]);
            }
        }

        if (more) {        // store prefetched sub+1 into the other stage
            char* d = fdst + (((sub + 1) & 1) ? STAGEB : 0);
            *(float4*)(d + 0 * TILEB) = pf0;
            *(float4*)(d + 1 * TILEB) = pf1;
            *(float4*)(d + 2 * TILEB) = pf2;
            *(float4*)(d + 3 * TILEB) = pf3;
        }
    }

    // ================= fused epilogue (R7-proven) =================
    const int laneq = lane >> 2, lane4 = lane & 3;
    int tr[4];
#pragma unroll
    for (int ri = 0; ri < 4; ri++)
        tr[ri] = s_ti[warp_m * 32 + (ri >> 1) * 16 + laneq + (ri & 1) * 8];

    float rps[4] = {0,0,0,0}, rns[4] = {0,0,0,0}, rpc[4] = {0,0,0,0}, rnc[4] = {0,0,0,0};

#pragma unroll
    for (int ni = 0; ni < 8; ni++) {
#pragma unroll
        for (int cb = 0; cb < 2; cb++) {
            const int col = warp_n * 64 + ni * 8 + lane4 * 2 + cb;
            const int tc = s_tj[col];
            float cps = 0.f, cns = 0.f, cpc = 0.f, cnc = 0.f;
#pragma unroll
            for (int mi = 0; mi < 2; mi++)
#pragma unroll
                for (int half = 0; half < 2; half++) {
                    const float sv = acc[mi][ni][half * 2 + cb];
                    const int ri = mi * 2 + half;
                    if (tr[ri] == tc) {
                        if (sv < 1.f) {
                            float p = softplus_f(-2.f * (sv - 0.5f));
                            rps[ri] += p; cps += p;
                            rpc[ri] += 1.f; cpc += 1.f;
                        }
                    } else {
                        float nterm = softplus_f(25.f * (sv - 0.5f));
                        rns[ri] += nterm; cns += nterm;
                        rnc[ri] += 1.f; cnc += 1.f;
                    }
                }
            if (offdiag) {
#pragma unroll
                for (int o = 4; o < 32; o <<= 1) {
                    cps += __shfl_xor_sync(0xffffffffu, cps, o);
                    cns += __shfl_xor_sync(0xffffffffu, cns, o);
                    cpc += __shfl_xor_sync(0xffffffffu, cpc, o);
                    cnc += __shfl_xor_sync(0xffffffffu, cnc, o);
                }
                if (laneq == 0) {
                    atomicAdd(&s_cns[col], cns);
                    atomicAdd(&s_cnc[col], cnc);
                    if (cpc != 0.f) {
                        atomicAdd(&s_cps[col], cps);
                        atomicAdd(&s_cpc[col], cpc);
                    }
                }
            }
        }
    }
#pragma unroll
    for (int ri = 0; ri < 4; ri++) {
        float p = rps[ri], a = rns[ri], q = rpc[ri], b = rnc[ri];
        p += __shfl_xor_sync(0xffffffffu, p, 1); p += __shfl_xor_sync(0xffffffffu, p, 2);
        a += __shfl_xor_sync(0xffffffffu, a, 1); a += __shfl_xor_sync(0xffffffffu, a, 2);
        q += __shfl_xor_sync(0xffffffffu, q, 1); q += __shfl_xor_sync(0xffffffffu, q, 2);
        b += __shfl_xor_sync(0xffffffffu, b, 1); b += __shfl_xor_sync(0xffffffffu, b, 2);
        if (lane4 == 0) {
            const int r = warp_m * 32 + (ri >> 1) * 16 + laneq + (ri & 1) * 8;
            atomicAdd(&s_rns[r], a);
            atomicAdd(&s_rnc[r], b);
            if (q != 0.f) {
                atomicAdd(&s_rps[r], p);
                atomicAdd(&s_rpc[r], q);
            }
        }
    }
    __syncthreads();

    if (tid < 128) {
        const int r = bi * BM + tid;
        atomicAdd(&g_ns[r], s_rns[tid]);
        atomicAdd(&g_nc[r], s_rnc[tid]);
        if (s_rpc[tid] != 0.f) {
            atomicAdd(&g_ps[r], s_rps[tid]);
            atomicAdd(&g_pc[r], s_rpc[tid]);
        }
    } else if (offdiag) {
        const int t2 = tid - 128;
        const int cidx = bj * BN + t2;
        atomicAdd(&g_ns[cidx], s_cns[t2]);
        atomicAdd(&g_nc[cidx], s_cnc[t2]);
        if (s_cpc[t2] != 0.f) {
            atomicAdd(&g_ps[cidx], s_cps[t2]);
            atomicAdd(&g_pc[cidx], s_cpc[t2]);
        }
    }
}

// ============================================================================
// finalize: per-row means; global mean
// ============================================================================
__global__ void __launch_bounds__(256) finalize_kernel(float* out) {
    __shared__ float red[256];
    float local = 0.f;
    for (int r = threadIdx.x; r < NROWS; r += 256) {
        float pc = g_pc[r], nc = g_nc[r];
        float pm = (pc > 0.f) ? g_ps[r] / fmaxf(pc, 1.f) : 0.f;
        float nm = (nc > 0.f) ? g_ns[r] / fmaxf(nc, 1.f) : 0.f;
        local += pm + nm;
    }
    red[threadIdx.x] = local;
    __syncthreads();
    for (int off = 128; off > 0; off >>= 1) {
        if (threadIdx.x < off) red[threadIdx.x] += red[threadIdx.x + off];
        __syncthreads();
    }
    if (threadIdx.x == 0) out[0] = red[0] / (float)NROWS;
}

extern "C" void kernel_launch(void* const* d_in, const int* in_sizes, int n_in,
                              void* d_out, int out_size) {
    const float* X = (const float*)d_in[0];
    const long long* tgt = (const long long*)d_in[1];
    float* out = (float*)d_out;

    prep_kernel<<<(NROWS * DDIM / 4 + 255) / 256, 256>>>(X);
    dim3 grid(NROWS / BN, NROWS / BM);
    sim_loss_mma<<<grid, 256>>>(tgt);
    finalize_kernel<<<1, 256>>>(out);
}

// round 11
// speedup vs baseline: 4.1616x; 1.0486x over previous
#include <cuda_runtime.h>
#include <cuda_bf16.h>
#include <math.h>
#include <stdint.h>

#define NROWS 4096
#define DDIM  512
#define BM 128
#define BN 128
#define NB (NROWS / BM)         // 32 tiles per dim
#define NTRI (NB * (NB + 1) / 2)   // 528 upper-triangle tiles
#define NSUB 32                 // 32 k16 sub-chunks (32 B per row each)
#define ROWB 32                 // smem row stride (XOR swizzle, no pad)
#define TILEB (128 * ROWB)      // 4096 B per operand tile
#define STAGEB (4 * TILEB)      // Ahi, Alo, Bhi, Blo = 16384 B

// ---- scratch (no cudaMalloc allowed) ----
__device__ __align__(16) __nv_bfloat16 g_hi[NROWS * DDIM];
__device__ __align__(16) __nv_bfloat16 g_lo[NROWS * DDIM];
__device__ float g_ps[NROWS];
__device__ float g_ns[NROWS];
__device__ float g_pc[NROWS];
__device__ float g_nc[NROWS];

__device__ __forceinline__ uint32_t smem_u32(const void* p) {
    return (uint32_t)__cvta_generic_to_shared(p);
}

__device__ __forceinline__ float softplus_f(float x) {
    return fmaxf(x, 0.f) + __logf(1.f + __expf(-fabsf(x)));
}

#define LDSM4(R, ADDR)                                                         \
    asm volatile("ldmatrix.sync.aligned.m8n8.x4.shared.b16 {%0,%1,%2,%3}, [%4];" \
                 : "=r"((R)[0]), "=r"((R)[1]), "=r"((R)[2]), "=r"((R)[3])      \
                 : "r"(ADDR))

#define MMA16816(C, A0, A1, A2, A3, B0, B1)                                    \
    asm volatile("mma.sync.aligned.m16n8k16.row.col.f32.bf16.bf16.f32 "        \
                 "{%0,%1,%2,%3}, {%4,%5,%6,%7}, {%8,%9}, {%0,%1,%2,%3};"       \
                 : "+f"((C)[0]), "+f"((C)[1]), "+f"((C)[2]), "+f"((C)[3])      \
                 : "r"(A0), "r"(A1), "r"(A2), "r"(A3), "r"(B0), "r"(B1))

// ============================================================================
// prep: fp32 -> bf16 hi/lo split; zeros per-row stat arrays
// ============================================================================
__global__ void __launch_bounds__(256) prep_kernel(const float* __restrict__ X) {
    int i = blockIdx.x * blockDim.x + threadIdx.x;
    int base = i * 4;
    if (base < NROWS * DDIM) {
        float4 v = *(const float4*)&X[base];
        float f[4] = {v.x, v.y, v.z, v.w};
#pragma unroll
        for (int k = 0; k < 4; k++) {
            __nv_bfloat16 h = __float2bfloat16(f[k]);
            g_hi[base + k] = h;
            g_lo[base + k] = __float2bfloat16(f[k] - __bfloat162float(h));
        }
    }
    if (i < NROWS) { g_ps[i] = 0.f; g_ns[i] = 0.f; g_pc[i] = 0.f; g_nc[i] = 0.f; }
}

// ============================================================================
// main: bf16 hi/lo-split mma.sync GEMM + fused softplus stats.
// Triangular grid: 528 CTAs, one per upper-triangle 128x128 tile.
// Static smem, double-buffered via register prefetch (LDG->reg->STS).
// ============================================================================
__global__ void __launch_bounds__(256, 2)
sim_loss_mma(const long long* __restrict__ tgt) {
    // triangular decode: blockIdx.x -> (bi, bj), bi <= bj
    const int t = (int)blockIdx.x;
    int bi = (int)((2.f * NB + 1.f - sqrtf((2.f * NB + 1.f) * (2.f * NB + 1.f)
                                           - 8.f * (float)t)) * 0.5f);
    // exact integer fixup (uniform across block)
    while (bi > 0 && bi * (2 * NB + 1 - bi) / 2 > t) bi--;
    while ((bi + 1) * (2 * NB + 1 - (bi + 1)) / 2 <= t) bi++;
    const int bj = bi + (t - bi * (2 * NB + 1 - bi) / 2);
    const bool offdiag = (bi != bj);

    __shared__ __align__(16) char s_tiles[2 * STAGEB];   // 32 KB, 2 stages
    __shared__ int   s_ti[128], s_tj[128];
    __shared__ float s_rps[128], s_rns[128], s_rpc[128], s_rnc[128];
    __shared__ float s_cps[128], s_cns[128], s_cpc[128], s_cnc[128];

    const int tid  = threadIdx.x;
    const int wid  = tid >> 5;
    const int lane = tid & 31;
    const int warp_m = wid & 3;    // 4 warps along M (32 rows each)
    const int warp_n = wid >> 2;   // 2 warps along N (64 cols each)

    if (tid < 128) {
        s_ti[tid] = (int)tgt[bi * BM + tid];
        s_rps[tid] = 0.f; s_rns[tid] = 0.f; s_rpc[tid] = 0.f; s_rnc[tid] = 0.f;
    } else {
        s_tj[tid - 128] = (int)tgt[bj * BN + tid - 128];
        s_cps[tid - 128] = 0.f; s_cns[tid - 128] = 0.f;
        s_cpc[tid - 128] = 0.f; s_cnc[tid - 128] = 0.f;
    }

    const char* src0 = (const char*)(g_hi + (size_t)bi * BM * DDIM);   // Ahi
    const char* src1 = (const char*)(g_lo + (size_t)bi * BM * DDIM);   // Alo
    const char* src2 = (const char*)(g_hi + (size_t)bj * BN * DDIM);   // Bhi
    const char* src3 = (const char*)(g_lo + (size_t)bj * BN * DDIM);   // Blo

    // per-thread fill coords: 128 rows x 2 sixteen-byte quads per tile
    const int frow = tid >> 1;
    const int fqb  = (tid & 1) * 16;
    const uint32_t fso = ((uint32_t)(frow * ROWB + fqb)) ^ (((uint32_t)frow & 4u) << 2);
    char* fdst = s_tiles + fso;
    const char* fsrc_base0 = src0 + frow * 1024 + fqb;
    const char* fsrc_base1 = src1 + frow * 1024 + fqb;
    const char* fsrc_base2 = src2 + frow * 1024 + fqb;
    const char* fsrc_base3 = src3 + frow * 1024 + fqb;

    const uint32_t stile = smem_u32(s_tiles);
    // ldmatrix lane offsets (XOR swizzle folded; +mi/+ng row steps preserve bit)
    const uint32_t a_off0 = (((uint32_t)((warp_m * 32 + (lane & 15)) * ROWB + (lane >> 4) * 16))
                             ^ (((uint32_t)lane & 4u) << 2));
    const int browb = warp_n * 64 + ((lane >> 4) << 3) + (lane & 7);
    const uint32_t b_off0 = (((uint32_t)(browb * ROWB + ((lane >> 3) & 1) * 16))
                             ^ (((uint32_t)lane & 4u) << 2));

    float acc[2][8][4];
#pragma unroll
    for (int mi = 0; mi < 2; mi++)
#pragma unroll
        for (int ni = 0; ni < 8; ni++)
#pragma unroll
            for (int x = 0; x < 4; x++) acc[mi][ni][x] = 0.f;

    // ---- prologue: fetch sub 0 and store into stage 0 ----
    float4 pf0 = *(const float4*)(fsrc_base0);
    float4 pf1 = *(const float4*)(fsrc_base1);
    float4 pf2 = *(const float4*)(fsrc_base2);
    float4 pf3 = *(const float4*)(fsrc_base3);
    *(float4*)(fdst + 0 * TILEB) = pf0;
    *(float4*)(fdst + 1 * TILEB) = pf1;
    *(float4*)(fdst + 2 * TILEB) = pf2;
    *(float4*)(fdst + 3 * TILEB) = pf3;

    for (int sub = 0; sub < NSUB; sub++) {
        __syncthreads();   // stage sub&1 fully written; stage^1 reads (iter sub-1) done

        const bool more = (sub + 1 < NSUB);
        if (more) {        // issue global loads early; consumed at bottom of loop
            const int go = (sub + 1) * 32;
            pf0 = *(const float4*)(fsrc_base0 + go);
            pf1 = *(const float4*)(fsrc_base1 + go);
            pf2 = *(const float4*)(fsrc_base2 + go);
            pf3 = *(const float4*)(fsrc_base3 + go);
        }

        const uint32_t st = stile + (uint32_t)(sub & 1) * STAGEB;
        uint32_t ah[2][4], al[2][4];
#pragma unroll
        for (int mi = 0; mi < 2; mi++) {
            const uint32_t ao = a_off0 + (uint32_t)(mi * 16 * ROWB);
            LDSM4(ah[mi], st + 0 * TILEB + ao);
            LDSM4(al[mi], st + 1 * TILEB + ao);
        }
#pragma unroll
        for (int ng = 0; ng < 4; ng++) {
            uint32_t bh[4], bl[4];
            const uint32_t bo = b_off0 + (uint32_t)(ng * 16 * ROWB);
            LDSM4(bh, st + 2 * TILEB + bo);
            LDSM4(bl, st + 3 * TILEB + bo);
#pragma unroll
            for (int mi = 0; mi < 2; mi++) {
                float* c0 = acc[mi][ng * 2 + 0];
                float* c1 = acc[mi][ng * 2 + 1];
                MMA16816(c0, ah[mi][0], ah[mi][1], ah[mi][2], ah[mi][3], bh[0], bh[1]);
                MMA16816(c1, ah[mi][0], ah[mi][1], ah[mi][2], ah[mi][3], bh[2], bh[3]);
                MMA16816(c0, ah[mi][0], ah[mi][1], ah[mi][2], ah[mi][3], bl[0], bl[1]);
                MMA16816(c1, ah[mi][0], ah[mi][1], ah[mi][2], ah[mi][3], bl[2], bl[3]);
                MMA16816(c0, al[mi][0], al[mi][1], al[mi][2], al[mi][3], bh[0], bh[1]);
                MMA16816(c1, al[mi][0], al[mi][1], al[mi][2], al[mi][3], bh[2], bh[3]);
            }
        }

        if (more) {        // store prefetched sub+1 into the other stage
            char* d = fdst + (((sub + 1) & 1) ? STAGEB : 0);
            *(float4*)(d + 0 * TILEB) = pf0;
            *(float4*)(d + 1 * TILEB) = pf1;
            *(float4*)(d + 2 * TILEB) = pf2;
            *(float4*)(d + 3 * TILEB) = pf3;
        }
    }

    // ================= fused epilogue (R7/R9-proven) =================
    const int laneq = lane >> 2, lane4 = lane & 3;
    int tr[4];
#pragma unroll
    for (int ri = 0; ri < 4; ri++)
        tr[ri] = s_ti[warp_m * 32 + (ri >> 1) * 16 + laneq + (ri & 1) * 8];

    float rps[4] = {0,0,0,0}, rns[4] = {0,0,0,0}, rpc[4] = {0,0,0,0}, rnc[4] = {0,0,0,0};

#pragma unroll
    for (int ni = 0; ni < 8; ni++) {
#pragma unroll
        for (int cb = 0; cb < 2; cb++) {
            const int col = warp_n * 64 + ni * 8 + lane4 * 2 + cb;
            const int tc = s_tj[col];
            float cps = 0.f, cns = 0.f, cpc = 0.f, cnc = 0.f;
#pragma unroll
            for (int mi = 0; mi < 2; mi++)
#pragma unroll
                for (int half = 0; half < 2; half++) {
                    const float sv = acc[mi][ni][half * 2 + cb];
                    const int ri = mi * 2 + half;
                    if (tr[ri] == tc) {
                        if (sv < 1.f) {
                            float p = softplus_f(-2.f * (sv - 0.5f));
                            rps[ri] += p; cps += p;
                            rpc[ri] += 1.f; cpc += 1.f;
                        }
                    } else {
                        float nterm = softplus_f(25.f * (sv - 0.5f));
                        rns[ri] += nterm; cns += nterm;
                        rnc[ri] += 1.f; cnc += 1.f;
                    }
                }
            if (offdiag) {
#pragma unroll
                for (int o = 4; o < 32; o <<= 1) {
                    cps += __shfl_xor_sync(0xffffffffu, cps, o);
                    cns += __shfl_xor_sync(0xffffffffu, cns, o);
                    cpc += __shfl_xor_sync(0xffffffffu, cpc, o);
                    cnc += __shfl_xor_sync(0xffffffffu, cnc, o);
                }
                if (laneq == 0) {
                    atomicAdd(&s_cns[col], cns);
                    atomicAdd(&s_cnc[col], cnc);
                    if (cpc != 0.f) {
                        atomicAdd(&s_cps[col], cps);
                        atomicAdd(&s_cpc[col], cpc);
                    }
                }
            }
        }
    }
#pragma unroll
    for (int ri = 0; ri < 4; ri++) {
        float p = rps[ri], a = rns[ri], q = rpc[ri], b = rnc[ri];
        p += __shfl_xor_sync(0xffffffffu, p, 1); p += __shfl_xor_sync(0xffffffffu, p, 2);
        a += __shfl_xor_sync(0xffffffffu, a, 1); a += __shfl_xor_sync(0xffffffffu, a, 2);
        q += __shfl_xor_sync(0xffffffffu, q, 1); q += __shfl_xor_sync(0xffffffffu, q, 2);
        b += __shfl_xor_sync(0xffffffffu, b, 1); b += __shfl_xor_sync(0xffffffffu, b, 2);
        if (lane4 == 0) {
            const int r = warp_m * 32 + (ri >> 1) * 16 + laneq + (ri & 1) * 8;
            atomicAdd(&s_rns[r], a);
            atomicAdd(&s_rnc[r], b);
            if (q != 0.f) {
                atomicAdd(&s_rps[r], p);
                atomicAdd(&s_rpc[r], q);
            }
        }
    }
    __syncthreads();

    if (tid < 128) {
        const int r = bi * BM + tid;
        atomicAdd(&g_ns[r], s_rns[tid]);
        atomicAdd(&g_nc[r], s_rnc[tid]);
        if (s_rpc[tid] != 0.f) {
            atomicAdd(&g_ps[r], s_rps[tid]);
            atomicAdd(&g_pc[r], s_rpc[tid]);
        }
    } else if (offdiag) {
        const int t2 = tid - 128;
        const int cidx = bj * BN + t2;
        atomicAdd(&g_ns[cidx], s_cns[t2]);
        atomicAdd(&g_nc[cidx], s_cnc[t2]);
        if (s_cpc[t2] != 0.f) {
            atomicAdd(&g_ps[cidx], s_cps[t2]);
            atomicAdd(&g_pc[cidx], s_cpc[t2]);
        }
    }
}

// ============================================================================
// finalize: per-row means; global mean
// ============================================================================
__global__ void __launch_bounds__(256) finalize_kernel(float* out) {
    __shared__ float red[256];
    float local = 0.f;
    for (int r = threadIdx.x; r < NROWS; r += 256) {
        float pc = g_pc[r], nc = g_nc[r];
        float pm = (pc > 0.f) ? g_ps[r] / fmaxf(pc, 1.f) : 0.f;
        float nm = (nc > 0.f) ? g_ns[r] / fmaxf(nc, 1.f) : 0.f;
        local += pm + nm;
    }
    red[threadIdx.x] = local;
    __syncthreads();
    for (int off = 128; off > 0; off >>= 1) {
        if (threadIdx.x < off) red[threadIdx.x] += red[threadIdx.x + off];
        __syncthreads();
    }
    if (threadIdx.x == 0) out[0] = red[0] / (float)NROWS;
}

extern "C" void kernel_launch(void* const* d_in, const int* in_sizes, int n_in,
                              void* d_out, int out_size) {
    const float* X = (const float*)d_in[0];
    const long long* tgt = (const long long*)d_in[1];
    float* out = (float*)d_out;

    prep_kernel<<<(NROWS * DDIM / 4 + 255) / 256, 256>>>(X);
    sim_loss_mma<<<NTRI, 256>>>(tgt);
    finalize_kernel<<<1, 256>>>(out);
}